// round 1
// baseline (speedup 1.0000x reference)
#include <cuda_runtime.h>
#include <cstdint>

// ---------------------------------------------------------------------------
// Scratch (device globals; allocation-free per harness rules)
// ---------------------------------------------------------------------------
#define MROWS (16384)   // B*n = 8*2048
#define DDIM  (512)

__device__ float g_H [MROWS * DDIM];   // mlp hidden (reused for x1 and x2)
__device__ float g_Km[MROWS * DDIM];   // k = mlp(x1)
__device__ float g_Qm[MROWS * DDIM];   // q = mlp(x2)
__device__ float g_QH[MROWS * DDIM];   // per-head q proj, col = h*64+e
__device__ float g_KH[MROWS * DDIM];
__device__ float g_VH[MROWS * DDIM];
__device__ float g_O [MROWS * DDIM];   // attention output, col = h*64+e

// ---------------------------------------------------------------------------
// Helpers
// ---------------------------------------------------------------------------
__device__ __forceinline__ float to_tf32(float x) {
    uint32_t u;
    asm("cvt.rna.tf32.f32 %0, %1;" : "=r"(u) : "f"(x));
    return __uint_as_float(u);
}
__device__ __forceinline__ uint32_t fbits(float x) { return __float_as_uint(x); }

// m16n8k8 tf32 mma, row.col, f32 accum
__device__ __forceinline__ void mma8(float* c, const uint32_t* a, const uint32_t* b) {
    asm volatile(
        "mma.sync.aligned.m16n8k8.row.col.f32.tf32.tf32.f32 "
        "{%0,%1,%2,%3}, {%4,%5,%6,%7}, {%8,%9}, {%0,%1,%2,%3};"
        : "+f"(c[0]), "+f"(c[1]), "+f"(c[2]), "+f"(c[3])
        : "r"(a[0]), "r"(a[1]), "r"(a[2]), "r"(a[3]), "r"(b[0]), "r"(b[1]));
}

// ---------------------------------------------------------------------------
// Generic GEMM: C[M,N] = act(A[M,K] @ op(B) + bias)
//   BMODE 0: B stored [N,K] row-major (ldb = K-stride)   (Wq/Wk/Wv stacked)
//   BMODE 1: B stored [K,N] row-major (ldb = N-stride)   (W1, W2) -> transpose
//   BMODE 2: B = Wo [H=8][512][64]; logical Bcol[n=d][k=h*64+e]
// Block tile 128x128, K tile 32, 256 threads, warp tile 32x64.
// M, N multiples of 128; K multiple of 32 (no bounds checks needed here).
// ---------------------------------------------------------------------------
template<int BMODE, bool RELU, bool BIAS>
__global__ __launch_bounds__(256, 2)
void gemm_kernel(const float* __restrict__ A, const float* __restrict__ Bm,
                 const float* __restrict__ bias, float* __restrict__ C,
                 int K, int lda, int ldb, int ldc)
{
    __shared__ float As[128][36];
    __shared__ float Bs[128][36];

    const int tid  = threadIdx.x;
    const int m0   = blockIdx.y * 128;
    const int n0   = blockIdx.x * 128;
    const int w    = tid >> 5;
    const int lane = tid & 31;
    const int qr   = lane >> 2;
    const int qc   = lane & 3;
    const int wm   = (w & 3) * 32;   // warp row offset
    const int wn   = (w >> 2) * 64;  // warp col offset

    float acc[2][8][4];
#pragma unroll
    for (int mt = 0; mt < 2; mt++)
#pragma unroll
        for (int nt = 0; nt < 8; nt++)
#pragma unroll
            for (int j = 0; j < 4; j++) acc[mt][nt][j] = 0.f;

    for (int k0 = 0; k0 < K; k0 += 32) {
        // --- load A tile [128 x 32] ---
#pragma unroll
        for (int i = 0; i < 4; i++) {
            int idx = tid + i * 256;
            int r = idx >> 3, c4 = (idx & 7) << 2;
            float4 v = *(const float4*)(A + (size_t)(m0 + r) * lda + k0 + c4);
            As[r][c4 + 0] = to_tf32(v.x);
            As[r][c4 + 1] = to_tf32(v.y);
            As[r][c4 + 2] = to_tf32(v.z);
            As[r][c4 + 3] = to_tf32(v.w);
        }
        // --- load B tile into Bs[n][k] ---
        if (BMODE == 1) {
#pragma unroll
            for (int i = 0; i < 4; i++) {
                int idx = tid + i * 256;
                int kk = idx >> 5, n4 = (idx & 31) << 2;
                float4 v = *(const float4*)(Bm + (size_t)(k0 + kk) * ldb + n0 + n4);
                Bs[n4 + 0][kk] = to_tf32(v.x);
                Bs[n4 + 1][kk] = to_tf32(v.y);
                Bs[n4 + 2][kk] = to_tf32(v.z);
                Bs[n4 + 3][kk] = to_tf32(v.w);
            }
        } else {
            const float* Bp;
            int ldbe;
            if (BMODE == 0) { Bp = Bm + (size_t)n0 * ldb + k0; ldbe = ldb; }
            else            { Bp = Bm + (size_t)(k0 >> 6) * 32768 + (size_t)n0 * 64 + (k0 & 63); ldbe = 64; }
#pragma unroll
            for (int i = 0; i < 4; i++) {
                int idx = tid + i * 256;
                int r = idx >> 3, c4 = (idx & 7) << 2;
                float4 v = *(const float4*)(Bp + (size_t)r * ldbe + c4);
                Bs[r][c4 + 0] = to_tf32(v.x);
                Bs[r][c4 + 1] = to_tf32(v.y);
                Bs[r][c4 + 2] = to_tf32(v.z);
                Bs[r][c4 + 3] = to_tf32(v.w);
            }
        }
        __syncthreads();

#pragma unroll
        for (int kk = 0; kk < 32; kk += 8) {
            uint32_t af[2][4], bf[8][2];
#pragma unroll
            for (int mt = 0; mt < 2; mt++) {
                int rb = wm + mt * 16;
                af[mt][0] = fbits(As[rb + qr][kk + qc]);
                af[mt][1] = fbits(As[rb + 8 + qr][kk + qc]);
                af[mt][2] = fbits(As[rb + qr][kk + 4 + qc]);
                af[mt][3] = fbits(As[rb + 8 + qr][kk + 4 + qc]);
            }
#pragma unroll
            for (int nt = 0; nt < 8; nt++) {
                int cb = wn + nt * 8;
                bf[nt][0] = fbits(Bs[cb + qr][kk + qc]);
                bf[nt][1] = fbits(Bs[cb + qr][kk + 4 + qc]);
            }
#pragma unroll
            for (int mt = 0; mt < 2; mt++)
#pragma unroll
                for (int nt = 0; nt < 8; nt++)
                    mma8(acc[mt][nt], af[mt], bf[nt]);
        }
        __syncthreads();
    }

    // --- epilogue ---
#pragma unroll
    for (int mt = 0; mt < 2; mt++) {
#pragma unroll
        for (int nt = 0; nt < 8; nt++) {
            int row = m0 + wm + mt * 16 + qr;
            int col = n0 + wn + nt * 8 + qc * 2;
            float b0 = BIAS ? bias[col]     : 0.f;
            float b1 = BIAS ? bias[col + 1] : 0.f;
            float v0 = acc[mt][nt][0] + b0;
            float v1 = acc[mt][nt][1] + b1;
            float v2 = acc[mt][nt][2] + b0;
            float v3 = acc[mt][nt][3] + b1;
            if (RELU) {
                v0 = fmaxf(v0, 0.f); v1 = fmaxf(v1, 0.f);
                v2 = fmaxf(v2, 0.f); v3 = fmaxf(v3, 0.f);
            }
            C[(size_t)row * ldc + col]           = v0;
            C[(size_t)row * ldc + col + 1]       = v1;
            C[(size_t)(row + 8) * ldc + col]     = v2;
            C[(size_t)(row + 8) * ldc + col + 1] = v3;
        }
    }
}

// ---------------------------------------------------------------------------
// Flash attention: per (b,h), Q tile 128, loop over 2048 keys in 64-chunks.
// QH/KH/VH layout [16384][512], head h occupies cols h*64..h*64+63.
// scores = (Q/8) @ K^T, online softmax, O += P @ V.
// ---------------------------------------------------------------------------
#define FL_SMEM ((128*68 + 64*68 + 64*68 + 128*68) * 4)

__global__ __launch_bounds__(256)
void flash_kernel(const float* __restrict__ QH, const float* __restrict__ KH,
                  const float* __restrict__ VH, float* __restrict__ O)
{
    extern __shared__ float sm[];
    float* Qs = sm;                 // [128][68]
    float* Ks = Qs + 128 * 68;      // [64][68]   Bcol form: Ks[n][k]
    float* Vt = Ks + 64 * 68;       // [64][68]   Bcol form: Vt[e][n]
    float* Ps = Vt + 64 * 68;       // [128][68]

    const int tid  = threadIdx.x;
    const int w    = tid >> 5;
    const int lane = tid & 31;
    const int qr   = lane >> 2;
    const int qc   = lane & 3;

    const int m0 = blockIdx.x * 128;
    const int bh = blockIdx.y;
    const size_t base = (size_t)(bh >> 3) * 2048 * 512 + (size_t)(bh & 7) * 64;

    const float* Qg = QH + base + (size_t)m0 * 512;

    // load Q tile (pre-scaled by 1/sqrt(hd) = 1/8)
#pragma unroll
    for (int i = 0; i < 8; i++) {
        int idx = tid + i * 256;
        int r = idx >> 4, c4 = (idx & 15) << 2;
        float4 v = *(const float4*)(Qg + (size_t)r * 512 + c4);
        Qs[r * 68 + c4 + 0] = to_tf32(v.x * 0.125f);
        Qs[r * 68 + c4 + 1] = to_tf32(v.y * 0.125f);
        Qs[r * 68 + c4 + 2] = to_tf32(v.z * 0.125f);
        Qs[r * 68 + c4 + 3] = to_tf32(v.w * 0.125f);
    }

    float mst[2] = {-1e30f, -1e30f};
    float lst[2] = {0.f, 0.f};
    float oacc[8][4];
#pragma unroll
    for (int et = 0; et < 8; et++)
#pragma unroll
        for (int j = 0; j < 4; j++) oacc[et][j] = 0.f;

    const int rA0 = (w * 16 + qr) * 68;
    const int rA1 = (w * 16 + 8 + qr) * 68;

    for (int it = 0; it < 32; ++it) {
        const int n0 = it * 64;
        __syncthreads();   // protect Ks/Vt/Ps reuse from previous iteration
        // load K tile [64 keys x 64] and V tile transposed
#pragma unroll
        for (int i = 0; i < 4; i++) {
            int idx = tid + i * 256;
            int r = idx >> 4, c4 = (idx & 15) << 2;
            float4 kv = *(const float4*)(KH + base + (size_t)(n0 + r) * 512 + c4);
            Ks[r * 68 + c4 + 0] = to_tf32(kv.x);
            Ks[r * 68 + c4 + 1] = to_tf32(kv.y);
            Ks[r * 68 + c4 + 2] = to_tf32(kv.z);
            Ks[r * 68 + c4 + 3] = to_tf32(kv.w);
            float4 vv = *(const float4*)(VH + base + (size_t)(n0 + r) * 512 + c4);
            Vt[(c4 + 0) * 68 + r] = to_tf32(vv.x);
            Vt[(c4 + 1) * 68 + r] = to_tf32(vv.y);
            Vt[(c4 + 2) * 68 + r] = to_tf32(vv.z);
            Vt[(c4 + 3) * 68 + r] = to_tf32(vv.w);
        }
        __syncthreads();

        // S = Qtile @ Ktile^T   (warp w owns query rows w*16..w*16+15)
        float s[8][4];
#pragma unroll
        for (int nt = 0; nt < 8; nt++)
#pragma unroll
            for (int j = 0; j < 4; j++) s[nt][j] = 0.f;
#pragma unroll
        for (int kk = 0; kk < 64; kk += 8) {
            uint32_t af[4] = { fbits(Qs[rA0 + kk + qc]), fbits(Qs[rA1 + kk + qc]),
                               fbits(Qs[rA0 + kk + 4 + qc]), fbits(Qs[rA1 + kk + 4 + qc]) };
#pragma unroll
            for (int nt = 0; nt < 8; nt++) {
                uint32_t bf[2] = { fbits(Ks[(nt * 8 + qr) * 68 + kk + qc]),
                                   fbits(Ks[(nt * 8 + qr) * 68 + kk + 4 + qc]) };
                mma8(s[nt], af, bf);
            }
        }

        // online softmax (thread covers rows r0 = w*16+qr and r0+8)
        float r0max = -1e30f, r1max = -1e30f;
#pragma unroll
        for (int nt = 0; nt < 8; nt++) {
            r0max = fmaxf(r0max, fmaxf(s[nt][0], s[nt][1]));
            r1max = fmaxf(r1max, fmaxf(s[nt][2], s[nt][3]));
        }
        r0max = fmaxf(r0max, __shfl_xor_sync(0xffffffffu, r0max, 1));
        r0max = fmaxf(r0max, __shfl_xor_sync(0xffffffffu, r0max, 2));
        r1max = fmaxf(r1max, __shfl_xor_sync(0xffffffffu, r1max, 1));
        r1max = fmaxf(r1max, __shfl_xor_sync(0xffffffffu, r1max, 2));

        float mn0 = fmaxf(mst[0], r0max), mn1 = fmaxf(mst[1], r1max);
        float al0 = __expf(mst[0] - mn0), al1 = __expf(mst[1] - mn1);
        float sum0 = 0.f, sum1 = 0.f;
#pragma unroll
        for (int nt = 0; nt < 8; nt++) {
            s[nt][0] = __expf(s[nt][0] - mn0); sum0 += s[nt][0];
            s[nt][1] = __expf(s[nt][1] - mn0); sum0 += s[nt][1];
            s[nt][2] = __expf(s[nt][2] - mn1); sum1 += s[nt][2];
            s[nt][3] = __expf(s[nt][3] - mn1); sum1 += s[nt][3];
        }
        sum0 += __shfl_xor_sync(0xffffffffu, sum0, 1);
        sum0 += __shfl_xor_sync(0xffffffffu, sum0, 2);
        sum1 += __shfl_xor_sync(0xffffffffu, sum1, 1);
        sum1 += __shfl_xor_sync(0xffffffffu, sum1, 2);

        lst[0] = lst[0] * al0 + sum0;  mst[0] = mn0;
        lst[1] = lst[1] * al1 + sum1;  mst[1] = mn1;
#pragma unroll
        for (int et = 0; et < 8; et++) {
            oacc[et][0] *= al0; oacc[et][1] *= al0;
            oacc[et][2] *= al1; oacc[et][3] *= al1;
        }

        // write P to smem (rows are warp-private)
#pragma unroll
        for (int nt = 0; nt < 8; nt++) {
            int c = nt * 8 + qc * 2;
            Ps[rA0 + c]     = to_tf32(s[nt][0]);
            Ps[rA0 + c + 1] = to_tf32(s[nt][1]);
            Ps[rA1 + c]     = to_tf32(s[nt][2]);
            Ps[rA1 + c + 1] = to_tf32(s[nt][3]);
        }
        __syncthreads();

        // O += P @ V
#pragma unroll
        for (int kk = 0; kk < 64; kk += 8) {
            uint32_t af[4] = { fbits(Ps[rA0 + kk + qc]), fbits(Ps[rA1 + kk + qc]),
                               fbits(Ps[rA0 + kk + 4 + qc]), fbits(Ps[rA1 + kk + 4 + qc]) };
#pragma unroll
            for (int et = 0; et < 8; et++) {
                uint32_t bf[2] = { fbits(Vt[(et * 8 + qr) * 68 + kk + qc]),
                                   fbits(Vt[(et * 8 + qr) * 68 + kk + 4 + qc]) };
                mma8(oacc[et], af, bf);
            }
        }
    }

    const float i0 = 1.f / lst[0];
    const float i1 = 1.f / lst[1];
    float* Og = O + base + (size_t)m0 * 512;
#pragma unroll
    for (int et = 0; et < 8; et++) {
        int c = et * 8 + qc * 2;
        Og[(size_t)(w * 16 + qr) * 512 + c]         = oacc[et][0] * i0;
        Og[(size_t)(w * 16 + qr) * 512 + c + 1]     = oacc[et][1] * i0;
        Og[(size_t)(w * 16 + 8 + qr) * 512 + c]     = oacc[et][2] * i1;
        Og[(size_t)(w * 16 + 8 + qr) * 512 + c + 1] = oacc[et][3] * i1;
    }
}

// ---------------------------------------------------------------------------
// Launch
// ---------------------------------------------------------------------------
extern "C" void kernel_launch(void* const* d_in, const int* in_sizes, int n_in,
                              void* d_out, int out_size)
{
    const float* x1 = (const float*)d_in[0];
    const float* x2 = (const float*)d_in[1];
    const float* r  = (const float*)d_in[2];
    const float* W1 = (const float*)d_in[3];
    const float* b1 = (const float*)d_in[4];
    const float* W2 = (const float*)d_in[5];
    const float* b2 = (const float*)d_in[6];
    const float* Wq = (const float*)d_in[7];
    const float* Wk = (const float*)d_in[8];
    const float* Wv = (const float*)d_in[9];
    const float* Wo = (const float*)d_in[10];
    float* out = (float*)d_out;

    float *H, *Km, *Qm, *QH, *KH, *VH, *Ob;
    cudaGetSymbolAddress((void**)&H,  g_H);
    cudaGetSymbolAddress((void**)&Km, g_Km);
    cudaGetSymbolAddress((void**)&Qm, g_Qm);
    cudaGetSymbolAddress((void**)&QH, g_QH);
    cudaGetSymbolAddress((void**)&KH, g_KH);
    cudaGetSymbolAddress((void**)&VH, g_VH);
    cudaGetSymbolAddress((void**)&Ob, g_O);

    cudaFuncSetAttribute(flash_kernel, cudaFuncAttributeMaxDynamicSharedMemorySize, FL_SMEM);

    dim3 gg(4, 128);   // N/128, M/128

    // k = mlp(x1), q = mlp(x2)   (H buffer reused; stream-ordered)
    gemm_kernel<1, true,  true ><<<gg, 256>>>(x1, W1, b1, H,  128, 128, 512, 512);
    gemm_kernel<1, false, true ><<<gg, 256>>>(H,  W2, b2, Km, 512, 512, 512, 512);
    gemm_kernel<1, true,  true ><<<gg, 256>>>(x2, W1, b1, H,  128, 128, 512, 512);
    gemm_kernel<1, false, true ><<<gg, 256>>>(H,  W2, b2, Qm, 512, 512, 512, 512);

    // per-head projections (Wq/Wk/Wv are [H*hd, d] = [512,512] row-major = Bcol)
    gemm_kernel<0, false, false><<<gg, 256>>>(Qm, Wq, nullptr, QH, 512, 512, 512, 512);
    gemm_kernel<0, false, false><<<gg, 256>>>(Km, Wk, nullptr, KH, 512, 512, 512, 512);
    gemm_kernel<0, false, false><<<gg, 256>>>(r,  Wv, nullptr, VH, 512, 512, 512, 512);

    // attention
    flash_kernel<<<dim3(16, 64), 256, FL_SMEM>>>(QH, KH, VH, Ob);

    // output projection: rep = O @ WoCat^T (Wo gather mode)
    gemm_kernel<2, false, false><<<gg, 256>>>(Ob, Wo, nullptr, out, 512, 512, 0, 512);
}

// round 5
// speedup vs baseline: 2.8458x; 2.8458x over previous
#include <cuda_runtime.h>
#include <cuda_fp16.h>
#include <cstdint>

// ---------------------------------------------------------------------------
// Scratch (device globals; allocation-free per harness rules)
// ---------------------------------------------------------------------------
#define MROWS 16384   // B*n = 8*2048

__device__ __half g_H  [MROWS * 512];  // mlp hidden (reused for x1 and x2)
__device__ __half g_Km [MROWS * 512];  // k = mlp(x1)
__device__ __half g_Qm [MROWS * 512];  // q = mlp(x2)
__device__ __half g_QH [MROWS * 512];  // per-head projections, col = h*64+e
__device__ __half g_KH [MROWS * 512];
__device__ __half g_VH [MROWS * 512];
__device__ __half g_O  [MROWS * 512];  // attention output
// fp16 copies of inputs / rearranged weights
__device__ __half g_x1h[MROWS * 128];
__device__ __half g_x2h[MROWS * 128];
__device__ __half g_rh [MROWS * 512];
__device__ __half g_W1t[512 * 128];    // W1^T -> [N=512][K=128]
__device__ __half g_W2t[512 * 512];    // W2^T -> [N=512][K=512]
__device__ __half g_Wqh[512 * 512];    // [n=h*64+e][k=d] (native layout)
__device__ __half g_Wkh[512 * 512];
__device__ __half g_Wvh[512 * 512];
__device__ __half g_Wot[512 * 512];    // [n=d][k=h*64+e] gathered from Wo

// ---------------------------------------------------------------------------
// Helpers
// ---------------------------------------------------------------------------
__device__ __forceinline__ uint32_t smem_u32(const void* p) {
    uint32_t a;
    asm("{ .reg .u64 t; cvta.to.shared.u64 t, %1; cvt.u32.u64 %0, t; }" : "=r"(a) : "l"(p));
    return a;
}
__device__ __forceinline__ uint32_t sw128(uint32_t o) { return o ^ ((o >> 3) & 0x70); }

__device__ __forceinline__ void cp_async16(uint32_t dst, const void* src) {
    asm volatile("cp.async.cg.shared.global [%0], [%1], 16;" :: "r"(dst), "l"(src) : "memory");
}
__device__ __forceinline__ void cp_commit() {
    asm volatile("cp.async.commit_group;" ::: "memory");
}
template<int N> __device__ __forceinline__ void cp_wait() {
    asm volatile("cp.async.wait_group %0;" :: "n"(N) : "memory");
}

__device__ __forceinline__ void ldmx4(uint32_t* r, uint32_t addr) {
    asm volatile("ldmatrix.sync.aligned.m8n8.x4.shared.b16 {%0,%1,%2,%3}, [%4];"
                 : "=r"(r[0]), "=r"(r[1]), "=r"(r[2]), "=r"(r[3]) : "r"(addr));
}
__device__ __forceinline__ void ldmx4t(uint32_t* r, uint32_t addr) {
    asm volatile("ldmatrix.sync.aligned.m8n8.x4.trans.shared.b16 {%0,%1,%2,%3}, [%4];"
                 : "=r"(r[0]), "=r"(r[1]), "=r"(r[2]), "=r"(r[3]) : "r"(addr));
}
// m16n8k16 fp16 mma, f32 accum
__device__ __forceinline__ void mma16(float* c, const uint32_t* a, const uint32_t* b) {
    asm volatile(
        "mma.sync.aligned.m16n8k16.row.col.f32.f16.f16.f32 "
        "{%0,%1,%2,%3}, {%4,%5,%6,%7}, {%8,%9}, {%0,%1,%2,%3};"
        : "+f"(c[0]), "+f"(c[1]), "+f"(c[2]), "+f"(c[3])
        : "r"(a[0]), "r"(a[1]), "r"(a[2]), "r"(a[3]), "r"(b[0]), "r"(b[1]));
}
__device__ __forceinline__ uint32_t packh2(float a, float b) {
    __half2 h = __floats2half2_rn(a, b);
    return *(uint32_t*)&h;
}

// ---------------------------------------------------------------------------
// Pre-pass kernels
// ---------------------------------------------------------------------------
__global__ void cvt_half(const float4* __restrict__ s, uint4* __restrict__ d, int n8) {
    int i = blockIdx.x * blockDim.x + threadIdx.x;
    if (i < n8) {
        float4 a = s[2 * i], b = s[2 * i + 1];
        uint4 u;
        u.x = packh2(a.x, a.y); u.y = packh2(a.z, a.w);
        u.z = packh2(b.x, b.y); u.w = packh2(b.z, b.w);
        d[i] = u;
    }
}
// S f32 [R][C] -> D f16 [C][R]
__global__ void transpose_half(const float* __restrict__ S, __half* __restrict__ D, int R, int C) {
    __shared__ __half t[32][33];
    int x = blockIdx.x * 32 + threadIdx.x;
    int y0 = blockIdx.y * 32;
#pragma unroll
    for (int j = 0; j < 32; j += 8)
        t[threadIdx.y + j][threadIdx.x] = __float2half(S[(size_t)(y0 + threadIdx.y + j) * C + x]);
    __syncthreads();
    int ox = y0 + threadIdx.x;
    int oy0 = blockIdx.x * 32;
#pragma unroll
    for (int j = 0; j < 32; j += 8)
        D[(size_t)(oy0 + threadIdx.y + j) * R + ox] = t[threadIdx.x][threadIdx.y + j];
}
// Wot[n][h*64+e] = Wo[h][n][e]   (Wo: [8][512][64] f32)
__global__ void wo_gather(const float* __restrict__ Wo, __half* __restrict__ D) {
    int i = blockIdx.x * blockDim.x + threadIdx.x;   // 512*512
    int n = i >> 9, k = i & 511;
    int h = k >> 6, e = k & 63;
    D[i] = __float2half(Wo[((size_t)h * 512 + n) * 64 + e]);
}

// ---------------------------------------------------------------------------
// fp16 GEMM: C[M,N] = act(A[M,K] @ B^T + bias)
//   A: [M][K] f16 row-major, B: [N][K] f16 row-major. K multiple of 64.
// CTA tile 128x128x64, 256 threads, warp tile 32x64, ldmatrix + mma.m16n8k16,
// swizzled cp.async double-buffered smem.
// ---------------------------------------------------------------------------
#define GSTAGE 32768          // A 16KB + B 16KB per stage
#define GEMM_SMEM (2 * GSTAGE)

template<bool RELU, bool BIAS, bool OUTF32>
__global__ __launch_bounds__(256, 2)
void gemm_h(const __half* __restrict__ A, const __half* __restrict__ B,
            const float* __restrict__ bias, void* __restrict__ Cout,
            int K, int ldc)
{
    extern __shared__ char smem[];
    const uint32_t sb = smem_u32(smem);
    const int tid = threadIdx.x, w = tid >> 5, lane = tid & 31;
    const int qr = lane >> 2, qc = lane & 3;
    const int m0 = blockIdx.y * 128, n0 = blockIdx.x * 128;
    const int wm = (w & 3) * 32, wn = (w >> 2) * 64;
    const int T = K >> 6;

    auto load_tile = [&](int t, int s) {
        uint32_t ab = sb + (uint32_t)s * GSTAGE, bb = ab + 16384;
        int k0 = t << 6;
#pragma unroll
        for (int i = 0; i < 4; i++) {
            int u = tid + i * 256;           // 0..1023
            int row = u >> 3, cu = u & 7;    // 16B unit in 128B row
            uint32_t sw = sw128((uint32_t)(row << 7) + (uint32_t)(cu << 4));
            cp_async16(ab + sw, A + (size_t)(m0 + row) * K + k0 + cu * 8);
            cp_async16(bb + sw, B + (size_t)(n0 + row) * K + k0 + cu * 8);
        }
    };

    float acc[2][8][4];
#pragma unroll
    for (int mt = 0; mt < 2; mt++)
#pragma unroll
        for (int nt = 0; nt < 8; nt++)
#pragma unroll
            for (int j = 0; j < 4; j++) acc[mt][nt][j] = 0.f;

    load_tile(0, 0);
    cp_commit();

    for (int t = 0; t < T; t++) {
        if (t + 1 < T) { load_tile(t + 1, (t + 1) & 1); cp_commit(); cp_wait<1>(); }
        else           { cp_wait<0>(); }
        __syncthreads();
        uint32_t ab = sb + (uint32_t)(t & 1) * GSTAGE, bb = ab + 16384;
#pragma unroll
        for (int j = 0; j < 4; j++) {
            uint32_t af[2][4], bf[8][2];
#pragma unroll
            for (int mt = 0; mt < 2; mt++) {
                int row = wm + mt * 16 + (lane & 7) + ((lane >> 3) & 1) * 8;
                int unit = 2 * j + (lane >> 4);
                ldmx4(af[mt], ab + sw128((uint32_t)(row << 7) + (uint32_t)(unit << 4)));
            }
#pragma unroll
            for (int p = 0; p < 4; p++) {
                uint32_t r[4];
                int row = wn + p * 16 + (lane & 7) + ((lane >> 4) & 1) * 8;
                int unit = 2 * j + ((lane >> 3) & 1);
                ldmx4(r, bb + sw128((uint32_t)(row << 7) + (uint32_t)(unit << 4)));
                bf[2 * p][0] = r[0]; bf[2 * p][1] = r[1];
                bf[2 * p + 1][0] = r[2]; bf[2 * p + 1][1] = r[3];
            }
#pragma unroll
            for (int mt = 0; mt < 2; mt++)
#pragma unroll
                for (int nt = 0; nt < 8; nt++)
                    mma16(acc[mt][nt], af[mt], bf[nt]);
        }
        __syncthreads();
    }

    // epilogue
#pragma unroll
    for (int mt = 0; mt < 2; mt++) {
#pragma unroll
        for (int nt = 0; nt < 8; nt++) {
            int row = m0 + wm + mt * 16 + qr;
            int col = n0 + wn + nt * 8 + qc * 2;
            float b0 = BIAS ? bias[col] : 0.f;
            float b1 = BIAS ? bias[col + 1] : 0.f;
            float v0 = acc[mt][nt][0] + b0, v1 = acc[mt][nt][1] + b1;
            float v2 = acc[mt][nt][2] + b0, v3 = acc[mt][nt][3] + b1;
            if (RELU) {
                v0 = fmaxf(v0, 0.f); v1 = fmaxf(v1, 0.f);
                v2 = fmaxf(v2, 0.f); v3 = fmaxf(v3, 0.f);
            }
            if (OUTF32) {
                float* C = (float*)Cout;
                *(float2*)(C + (size_t)row * ldc + col)       = make_float2(v0, v1);
                *(float2*)(C + (size_t)(row + 8) * ldc + col) = make_float2(v2, v3);
            } else {
                __half* C = (__half*)Cout;
                *(uint32_t*)(C + (size_t)row * ldc + col)       = packh2(v0, v1);
                *(uint32_t*)(C + (size_t)(row + 8) * ldc + col) = packh2(v2, v3);
            }
        }
    }
}

// ---------------------------------------------------------------------------
// Flash attention, fp16 mma: per (b,h), Q tile 128, 2048 keys in 64-chunks.
// Q a-frags cached in registers; P never touches smem (C-frag -> A-frag repack).
// smem: Q 16KB + 2 stages of (K 8KB + V 8KB) = 48KB.
// ---------------------------------------------------------------------------
#define FL_SMEM (16384 + 2 * 16384)

__global__ __launch_bounds__(256, 2)
void flash_h(const __half* __restrict__ QH, const __half* __restrict__ KH,
             const __half* __restrict__ VH, __half* __restrict__ O)
{
    extern __shared__ char smc[];
    const uint32_t sb = smem_u32(smc);
    const int tid  = threadIdx.x;
    const int w    = tid >> 5;
    const int lane = tid & 31;
    const int qr   = lane >> 2;
    const int qc   = lane & 3;

    const int m0 = blockIdx.x * 128;
    const int bh = blockIdx.y;
    const size_t base = (size_t)(bh >> 3) * 2048 * 512 + (size_t)(bh & 7) * 64;

    // ---- Q tile: 128 rows x 64 halves (128B rows), swizzled ----
    {
        const __half* Qg = QH + base + (size_t)m0 * 512;
#pragma unroll
        for (int i = 0; i < 4; i++) {
            int u = tid + i * 256;
            int row = u >> 3, cu = u & 7;
            cp_async16(sb + sw128((uint32_t)(row << 7) + (uint32_t)(cu << 4)),
                       Qg + (size_t)row * 512 + cu * 8);
        }
        cp_commit();
    }
    // ---- KV tiles ----
    auto load_kv = [&](int it, int s) {
        uint32_t kb = sb + 16384u + (uint32_t)s * 16384u;
        uint32_t vb = kb + 8192u;
        const __half* Kg = KH + base + (size_t)(it * 64) * 512;
        const __half* Vg = VH + base + (size_t)(it * 64) * 512;
#pragma unroll
        for (int i = 0; i < 2; i++) {
            int u = tid + i * 256;           // 0..511
            int row = u >> 3, cu = u & 7;
            uint32_t sw = sw128((uint32_t)(row << 7) + (uint32_t)(cu << 4));
            cp_async16(kb + sw, Kg + (size_t)row * 512 + cu * 8);
            cp_async16(vb + sw, Vg + (size_t)row * 512 + cu * 8);
        }
    };
    load_kv(0, 0);
    cp_commit();
    cp_wait<0>();
    __syncthreads();

    // ---- preload Q a-frags (warp w owns q-rows w*16..w*16+15) ----
    uint32_t aQ[4][4];
#pragma unroll
    for (int j = 0; j < 4; j++) {
        int row = w * 16 + (lane & 7) + ((lane >> 3) & 1) * 8;
        int unit = 2 * j + (lane >> 4);
        ldmx4(aQ[j], sb + sw128((uint32_t)(row << 7) + (uint32_t)(unit << 4)));
    }

    float mst[2] = {-1e30f, -1e30f};
    float lst[2] = {0.f, 0.f};
    float oacc[8][4];
#pragma unroll
    for (int et = 0; et < 8; et++)
#pragma unroll
        for (int j = 0; j < 4; j++) oacc[et][j] = 0.f;

    for (int it = 0; it < 32; ++it) {
        const int s = it & 1;
        if (it + 1 < 32) { load_kv(it + 1, s ^ 1); cp_commit(); cp_wait<1>(); }
        else             { cp_wait<0>(); }
        __syncthreads();

        uint32_t kb = sb + 16384u + (uint32_t)s * 16384u;
        uint32_t vb = kb + 8192u;

        // ---- S = Q @ K^T ----
        float s_[8][4];
#pragma unroll
        for (int nt = 0; nt < 8; nt++)
#pragma unroll
            for (int j = 0; j < 4; j++) s_[nt][j] = 0.f;
#pragma unroll
        for (int j = 0; j < 4; j++) {
            uint32_t bf[8][2];
#pragma unroll
            for (int p = 0; p < 4; p++) {
                uint32_t r[4];
                int row = p * 16 + (lane & 7) + ((lane >> 4) & 1) * 8;
                int unit = 2 * j + ((lane >> 3) & 1);
                ldmx4(r, kb + sw128((uint32_t)(row << 7) + (uint32_t)(unit << 4)));
                bf[2 * p][0] = r[0]; bf[2 * p][1] = r[1];
                bf[2 * p + 1][0] = r[2]; bf[2 * p + 1][1] = r[3];
            }
#pragma unroll
            for (int nt = 0; nt < 8; nt++)
                mma16(s_[nt], aQ[j], bf[nt]);
        }
#pragma unroll
        for (int nt = 0; nt < 8; nt++) {
            s_[nt][0] *= 0.125f; s_[nt][1] *= 0.125f;
            s_[nt][2] *= 0.125f; s_[nt][3] *= 0.125f;
        }

        // ---- online softmax: thread covers rows (w*16+qr) and (+8) ----
        float r0max = -1e30f, r1max = -1e30f;
#pragma unroll
        for (int nt = 0; nt < 8; nt++) {
            r0max = fmaxf(r0max, fmaxf(s_[nt][0], s_[nt][1]));
            r1max = fmaxf(r1max, fmaxf(s_[nt][2], s_[nt][3]));
        }
        r0max = fmaxf(r0max, __shfl_xor_sync(0xffffffffu, r0max, 1));
        r0max = fmaxf(r0max, __shfl_xor_sync(0xffffffffu, r0max, 2));
        r1max = fmaxf(r1max, __shfl_xor_sync(0xffffffffu, r1max, 1));
        r1max = fmaxf(r1max, __shfl_xor_sync(0xffffffffu, r1max, 2));

        float mn0 = fmaxf(mst[0], r0max), mn1 = fmaxf(mst[1], r1max);
        float al0 = __expf(mst[0] - mn0), al1 = __expf(mst[1] - mn1);
        float sum0 = 0.f, sum1 = 0.f;
#pragma unroll
        for (int nt = 0; nt < 8; nt++) {
            s_[nt][0] = __expf(s_[nt][0] - mn0); sum0 += s_[nt][0];
            s_[nt][1] = __expf(s_[nt][1] - mn0); sum0 += s_[nt][1];
            s_[nt][2] = __expf(s_[nt][2] - mn1); sum1 += s_[nt][2];
            s_[nt][3] = __expf(s_[nt][3] - mn1); sum1 += s_[nt][3];
        }
        sum0 += __shfl_xor_sync(0xffffffffu, sum0, 1);
        sum0 += __shfl_xor_sync(0xffffffffu, sum0, 2);
        sum1 += __shfl_xor_sync(0xffffffffu, sum1, 1);
        sum1 += __shfl_xor_sync(0xffffffffu, sum1, 2);

        lst[0] = lst[0] * al0 + sum0;  mst[0] = mn0;
        lst[1] = lst[1] * al1 + sum1;  mst[1] = mn1;
#pragma unroll
        for (int et = 0; et < 8; et++) {
            oacc[et][0] *= al0; oacc[et][1] *= al0;
            oacc[et][2] *= al1; oacc[et][3] *= al1;
        }

        // ---- O += P @ V  (P stays in registers: C-frag -> A-frag repack) ----
#pragma unroll
        for (int j2 = 0; j2 < 4; j2++) {
            uint32_t pa[4] = {
                packh2(s_[2 * j2][0],     s_[2 * j2][1]),
                packh2(s_[2 * j2][2],     s_[2 * j2][3]),
                packh2(s_[2 * j2 + 1][0], s_[2 * j2 + 1][1]),
                packh2(s_[2 * j2 + 1][2], s_[2 * j2 + 1][3])
            };
#pragma unroll
            for (int p = 0; p < 4; p++) {
                uint32_t r[4];
                int row = j2 * 16 + (lane & 7) + ((lane >> 3) & 1) * 8;  // key rows
                int unit = p * 2 + (lane >> 4);                           // e-units
                ldmx4t(r, vb + sw128((uint32_t)(row << 7) + (uint32_t)(unit << 4)));
                uint32_t bf0[2] = { r[0], r[1] };
                uint32_t bf1[2] = { r[2], r[3] };
                mma16(oacc[2 * p],     pa, bf0);
                mma16(oacc[2 * p + 1], pa, bf1);
            }
        }
        __syncthreads();
    }

    const float i0 = 1.f / lst[0];
    const float i1 = 1.f / lst[1];
    __half* Og = O + base + (size_t)m0 * 512;
#pragma unroll
    for (int et = 0; et < 8; et++) {
        int c = et * 8 + qc * 2;
        *(uint32_t*)(Og + (size_t)(w * 16 + qr) * 512 + c)     = packh2(oacc[et][0] * i0, oacc[et][1] * i0);
        *(uint32_t*)(Og + (size_t)(w * 16 + 8 + qr) * 512 + c) = packh2(oacc[et][2] * i1, oacc[et][3] * i1);
    }
}

// ---------------------------------------------------------------------------
// Launch
// ---------------------------------------------------------------------------
extern "C" void kernel_launch(void* const* d_in, const int* in_sizes, int n_in,
                              void* d_out, int out_size)
{
    const float* x1 = (const float*)d_in[0];
    const float* x2 = (const float*)d_in[1];
    const float* r  = (const float*)d_in[2];
    const float* W1 = (const float*)d_in[3];
    const float* b1 = (const float*)d_in[4];
    const float* W2 = (const float*)d_in[5];
    const float* b2 = (const float*)d_in[6];
    const float* Wq = (const float*)d_in[7];
    const float* Wk = (const float*)d_in[8];
    const float* Wv = (const float*)d_in[9];
    const float* Wo = (const float*)d_in[10];
    float* out = (float*)d_out;

    __half *H, *Km, *Qm, *QH, *KH, *VH, *Ob;
    __half *x1h, *x2h, *rh, *W1t, *W2t, *Wqh, *Wkh, *Wvh, *Wot;
    cudaGetSymbolAddress((void**)&H,   g_H);
    cudaGetSymbolAddress((void**)&Km,  g_Km);
    cudaGetSymbolAddress((void**)&Qm,  g_Qm);
    cudaGetSymbolAddress((void**)&QH,  g_QH);
    cudaGetSymbolAddress((void**)&KH,  g_KH);
    cudaGetSymbolAddress((void**)&VH,  g_VH);
    cudaGetSymbolAddress((void**)&Ob,  g_O);
    cudaGetSymbolAddress((void**)&x1h, g_x1h);
    cudaGetSymbolAddress((void**)&x2h, g_x2h);
    cudaGetSymbolAddress((void**)&rh,  g_rh);
    cudaGetSymbolAddress((void**)&W1t, g_W1t);
    cudaGetSymbolAddress((void**)&W2t, g_W2t);
    cudaGetSymbolAddress((void**)&Wqh, g_Wqh);
    cudaGetSymbolAddress((void**)&Wkh, g_Wkh);
    cudaGetSymbolAddress((void**)&Wvh, g_Wvh);
    cudaGetSymbolAddress((void**)&Wot, g_Wot);

    cudaFuncSetAttribute(flash_h, cudaFuncAttributeMaxDynamicSharedMemorySize, FL_SMEM);
    cudaFuncSetAttribute((const void*)gemm_h<true,  true,  false>, cudaFuncAttributeMaxDynamicSharedMemorySize, GEMM_SMEM);
    cudaFuncSetAttribute((const void*)gemm_h<false, true,  false>, cudaFuncAttributeMaxDynamicSharedMemorySize, GEMM_SMEM);
    cudaFuncSetAttribute((const void*)gemm_h<false, false, false>, cudaFuncAttributeMaxDynamicSharedMemorySize, GEMM_SMEM);
    cudaFuncSetAttribute((const void*)gemm_h<false, false, true >, cudaFuncAttributeMaxDynamicSharedMemorySize, GEMM_SMEM);

    // --- pre-pass: fp16 conversion / weight rearrangement ---
    cvt_half<<<(MROWS * 128 / 8 + 255) / 256, 256>>>((const float4*)x1, (uint4*)x1h, MROWS * 128 / 8);
    cvt_half<<<(MROWS * 128 / 8 + 255) / 256, 256>>>((const float4*)x2, (uint4*)x2h, MROWS * 128 / 8);
    cvt_half<<<(MROWS * 512 / 8 + 255) / 256, 256>>>((const float4*)r,  (uint4*)rh,  MROWS * 512 / 8);
    cvt_half<<<(512 * 512 / 8 + 255) / 256, 256>>>((const float4*)Wq, (uint4*)Wqh, 512 * 512 / 8);
    cvt_half<<<(512 * 512 / 8 + 255) / 256, 256>>>((const float4*)Wk, (uint4*)Wkh, 512 * 512 / 8);
    cvt_half<<<(512 * 512 / 8 + 255) / 256, 256>>>((const float4*)Wv, (uint4*)Wvh, 512 * 512 / 8);
    transpose_half<<<dim3(16, 4),  dim3(32, 8)>>>(W1, W1t, 128, 512);
    transpose_half<<<dim3(16, 16), dim3(32, 8)>>>(W2, W2t, 512, 512);
    wo_gather<<<512 * 512 / 256, 256>>>(Wo, Wot);

    dim3 gg(4, 128);   // N/128, M/128

    // k = mlp(x1), q = mlp(x2)
    gemm_h<true,  true,  false><<<gg, 256, GEMM_SMEM>>>(x1h, W1t, b1, H,  128, 512);
    gemm_h<false, true,  false><<<gg, 256, GEMM_SMEM>>>(H,   W2t, b2, Km, 512, 512);
    gemm_h<true,  true,  false><<<gg, 256, GEMM_SMEM>>>(x2h, W1t, b1, H,  128, 512);
    gemm_h<false, true,  false><<<gg, 256, GEMM_SMEM>>>(H,   W2t, b2, Qm, 512, 512);

    // per-head projections
    gemm_h<false, false, false><<<gg, 256, GEMM_SMEM>>>(Qm, Wqh, nullptr, QH, 512, 512);
    gemm_h<false, false, false><<<gg, 256, GEMM_SMEM>>>(Km, Wkh, nullptr, KH, 512, 512);
    gemm_h<false, false, false><<<gg, 256, GEMM_SMEM>>>(rh, Wvh, nullptr, VH, 512, 512);

    // attention
    flash_h<<<dim3(16, 64), 256, FL_SMEM>>>(QH, KH, VH, Ob);

    // output projection: rep = O @ Wot^T  (f32 out)
    gemm_h<false, false, true ><<<gg, 256, GEMM_SMEM>>>(Ob, Wot, nullptr, out, 512, 512);
}

// round 6
// speedup vs baseline: 3.2869x; 1.1550x over previous
#include <cuda_runtime.h>
#include <cuda_fp16.h>
#include <cstdint>

// ---------------------------------------------------------------------------
// Scratch (device globals; allocation-free per harness rules)
// ---------------------------------------------------------------------------
#define MROWS 16384   // B*n = 8*2048

__device__ __half g_H1 [MROWS * 512];  // mlp hidden for x1
__device__ __half g_H2 [MROWS * 512];  // mlp hidden for x2
__device__ __half g_Km [MROWS * 512];  // k = mlp(x1)
__device__ __half g_Qm [MROWS * 512];  // q = mlp(x2)
__device__ __half g_QH [MROWS * 512];  // per-head projections, col = h*64+e
__device__ __half g_KH [MROWS * 512];
__device__ __half g_VH [MROWS * 512];
__device__ __half g_O  [MROWS * 512];  // attention output
__device__ __half g_x1h[MROWS * 128];
__device__ __half g_x2h[MROWS * 128];
__device__ __half g_rh [MROWS * 512];
__device__ __half g_W1t[512 * 128];    // W1^T -> [N=512][K=128]
__device__ __half g_W2t[512 * 512];    // W2^T -> [N=512][K=512]
__device__ __half g_Wqh[512 * 512];    // [n=h*64+e][k=d] (native layout)
__device__ __half g_Wkh[512 * 512];
__device__ __half g_Wvh[512 * 512];
__device__ __half g_Wot[512 * 512];    // [n=d][k=h*64+e] gathered from Wo

// ---------------------------------------------------------------------------
// Helpers
// ---------------------------------------------------------------------------
__device__ __forceinline__ uint32_t smem_u32(const void* p) {
    uint32_t a;
    asm("{ .reg .u64 t; cvta.to.shared.u64 t, %1; cvt.u32.u64 %0, t; }" : "=r"(a) : "l"(p));
    return a;
}
__device__ __forceinline__ uint32_t sw128(uint32_t o) { return o ^ ((o >> 3) & 0x70); }

__device__ __forceinline__ void cp_async16(uint32_t dst, const void* src) {
    asm volatile("cp.async.cg.shared.global [%0], [%1], 16;" :: "r"(dst), "l"(src) : "memory");
}
__device__ __forceinline__ void cp_commit() {
    asm volatile("cp.async.commit_group;" ::: "memory");
}
template<int N> __device__ __forceinline__ void cp_wait() {
    asm volatile("cp.async.wait_group %0;" :: "n"(N) : "memory");
}

__device__ __forceinline__ void ldmx4(uint32_t* r, uint32_t addr) {
    asm volatile("ldmatrix.sync.aligned.m8n8.x4.shared.b16 {%0,%1,%2,%3}, [%4];"
                 : "=r"(r[0]), "=r"(r[1]), "=r"(r[2]), "=r"(r[3]) : "r"(addr));
}
__device__ __forceinline__ void ldmx4t(uint32_t* r, uint32_t addr) {
    asm volatile("ldmatrix.sync.aligned.m8n8.x4.trans.shared.b16 {%0,%1,%2,%3}, [%4];"
                 : "=r"(r[0]), "=r"(r[1]), "=r"(r[2]), "=r"(r[3]) : "r"(addr));
}
__device__ __forceinline__ void mma16(float* c, const uint32_t* a, const uint32_t* b) {
    asm volatile(
        "mma.sync.aligned.m16n8k16.row.col.f32.f16.f16.f32 "
        "{%0,%1,%2,%3}, {%4,%5,%6,%7}, {%8,%9}, {%0,%1,%2,%3};"
        : "+f"(c[0]), "+f"(c[1]), "+f"(c[2]), "+f"(c[3])
        : "r"(a[0]), "r"(a[1]), "r"(a[2]), "r"(a[3]), "r"(b[0]), "r"(b[1]));
}
__device__ __forceinline__ uint32_t packh2(float a, float b) {
    __half2 h = __floats2half2_rn(a, b);
    return *(uint32_t*)&h;
}
__device__ __forceinline__ uint32_t h2exp2(uint32_t x) {
    uint32_t y;
    asm("ex2.approx.f16x2 %0, %1;" : "=r"(y) : "r"(x));
    return y;
}
__device__ __forceinline__ float2 h2tof2(uint32_t x) {
    __half2 h = *(__half2*)&x;
    return __half22float2(h);
}

// ---------------------------------------------------------------------------
// Pre-pass kernels (2 launches total)
// ---------------------------------------------------------------------------
// grid (1024, 1, 3), block 256: z=0 x1, z=1 x2, z=2 r
__global__ void prep_inputs(const float4* __restrict__ x1, const float4* __restrict__ x2,
                            const float4* __restrict__ r,
                            uint4* __restrict__ x1h, uint4* __restrict__ x2h,
                            uint4* __restrict__ rh)
{
    const int z = blockIdx.z;
    const float4* S = (z == 0) ? x1 : (z == 1) ? x2 : r;
    uint4* D = (z == 0) ? x1h : (z == 1) ? x2h : rh;
    const int n8 = (z == 2) ? (MROWS * 512 / 8) : (MROWS * 128 / 8);
    for (int i = blockIdx.x * 256 + threadIdx.x; i < n8; i += 262144) {
        float4 a = S[2 * i], b = S[2 * i + 1];
        uint4 u;
        u.x = packh2(a.x, a.y); u.y = packh2(a.z, a.w);
        u.z = packh2(b.x, b.y); u.w = packh2(b.z, b.w);
        D[i] = u;
    }
}
// grid (128, 1, 6), block 256
__global__ void prep_weights(const float* __restrict__ W1, const float* __restrict__ W2,
                             const float* __restrict__ Wq, const float* __restrict__ Wk,
                             const float* __restrict__ Wv, const float* __restrict__ Wo,
                             __half* __restrict__ W1t, __half* __restrict__ W2t,
                             __half* __restrict__ Wqh, __half* __restrict__ Wkh,
                             __half* __restrict__ Wvh, __half* __restrict__ Wot)
{
    const int z = blockIdx.z;
    const int t0 = blockIdx.x * 256 + threadIdx.x;   // 0..32767
    if (z == 0) { for (int i = t0; i < 262144; i += 32768) Wqh[i] = __float2half(Wq[i]); }
    else if (z == 1) { for (int i = t0; i < 262144; i += 32768) Wkh[i] = __float2half(Wk[i]); }
    else if (z == 2) { for (int i = t0; i < 262144; i += 32768) Wvh[i] = __float2half(Wv[i]); }
    else if (z == 3) {
        for (int i = t0; i < 262144; i += 32768) {
            int n = i >> 9, k = i & 511, h = k >> 6, e = k & 63;
            Wot[i] = __float2half(Wo[((size_t)h * 512 + n) * 64 + e]);
        }
    } else if (z == 4) {
        for (int i = t0; i < 65536; i += 32768) {
            int n = i >> 7, k = i & 127;
            W1t[i] = __float2half(W1[(size_t)k * 512 + n]);
        }
    } else {
        for (int i = t0; i < 262144; i += 32768) {
            int n = i >> 9, k = i & 511;
            W2t[i] = __float2half(W2[(size_t)k * 512 + n]);
        }
    }
}

// ---------------------------------------------------------------------------
// Batched fp16 GEMM: C[M,N] = act(A[M,K] @ B^T + bias), z selects (A,B,C)
//   A: [M][K] f16 row-major, B: [N][K] f16 row-major. K multiple of 64.
// CTA tile 128x128x64, 256 threads, warp tile 32x64, double-buffered cp.async.
// ---------------------------------------------------------------------------
#define GSTAGE 32768
#define GEMM_SMEM (2 * GSTAGE)

template<bool RELU, bool BIAS, bool OUTF32>
__global__ __launch_bounds__(256, 2)
void gemm_hb(const __half* __restrict__ A0, const __half* __restrict__ A1, const __half* __restrict__ A2,
             const __half* __restrict__ B0, const __half* __restrict__ B1, const __half* __restrict__ B2,
             const float* __restrict__ bias,
             void* __restrict__ C0, void* __restrict__ C1, void* __restrict__ C2,
             int K, int ldc)
{
    const int z = blockIdx.z;
    const __half* A = (z == 0) ? A0 : (z == 1) ? A1 : A2;
    const __half* B = (z == 0) ? B0 : (z == 1) ? B1 : B2;
    void* Cout     = (z == 0) ? C0 : (z == 1) ? C1 : C2;

    extern __shared__ char smem[];
    const uint32_t sb = smem_u32(smem);
    const int tid = threadIdx.x, w = tid >> 5, lane = tid & 31;
    const int qr = lane >> 2, qc = lane & 3;
    const int m0 = blockIdx.y * 128, n0 = blockIdx.x * 128;
    const int wm = (w & 3) * 32, wn = (w >> 2) * 64;
    const int T = K >> 6;

    auto load_tile = [&](int t, int s) {
        uint32_t ab = sb + (uint32_t)s * GSTAGE, bb = ab + 16384;
        int k0 = t << 6;
#pragma unroll
        for (int i = 0; i < 4; i++) {
            int u = tid + i * 256;
            int row = u >> 3, cu = u & 7;
            uint32_t sw = sw128((uint32_t)(row << 7) + (uint32_t)(cu << 4));
            cp_async16(ab + sw, A + (size_t)(m0 + row) * K + k0 + cu * 8);
            cp_async16(bb + sw, B + (size_t)(n0 + row) * K + k0 + cu * 8);
        }
    };

    float acc[2][8][4];
#pragma unroll
    for (int mt = 0; mt < 2; mt++)
#pragma unroll
        for (int nt = 0; nt < 8; nt++)
#pragma unroll
            for (int j = 0; j < 4; j++) acc[mt][nt][j] = 0.f;

    load_tile(0, 0);
    cp_commit();

    for (int t = 0; t < T; t++) {
        if (t + 1 < T) { load_tile(t + 1, (t + 1) & 1); cp_commit(); cp_wait<1>(); }
        else           { cp_wait<0>(); }
        __syncthreads();
        uint32_t ab = sb + (uint32_t)(t & 1) * GSTAGE, bb = ab + 16384;
#pragma unroll
        for (int j = 0; j < 4; j++) {
            uint32_t af[2][4], bf[8][2];
#pragma unroll
            for (int mt = 0; mt < 2; mt++) {
                int row = wm + mt * 16 + (lane & 7) + ((lane >> 3) & 1) * 8;
                int unit = 2 * j + (lane >> 4);
                ldmx4(af[mt], ab + sw128((uint32_t)(row << 7) + (uint32_t)(unit << 4)));
            }
#pragma unroll
            for (int p = 0; p < 4; p++) {
                uint32_t r[4];
                int row = wn + p * 16 + (lane & 7) + ((lane >> 4) & 1) * 8;
                int unit = 2 * j + ((lane >> 3) & 1);
                ldmx4(r, bb + sw128((uint32_t)(row << 7) + (uint32_t)(unit << 4)));
                bf[2 * p][0] = r[0]; bf[2 * p][1] = r[1];
                bf[2 * p + 1][0] = r[2]; bf[2 * p + 1][1] = r[3];
            }
#pragma unroll
            for (int mt = 0; mt < 2; mt++)
#pragma unroll
                for (int nt = 0; nt < 8; nt++)
                    mma16(acc[mt][nt], af[mt], bf[nt]);
        }
        __syncthreads();
    }

#pragma unroll
    for (int mt = 0; mt < 2; mt++) {
#pragma unroll
        for (int nt = 0; nt < 8; nt++) {
            int row = m0 + wm + mt * 16 + qr;
            int col = n0 + wn + nt * 8 + qc * 2;
            float b0 = BIAS ? bias[col] : 0.f;
            float b1 = BIAS ? bias[col + 1] : 0.f;
            float v0 = acc[mt][nt][0] + b0, v1 = acc[mt][nt][1] + b1;
            float v2 = acc[mt][nt][2] + b0, v3 = acc[mt][nt][3] + b1;
            if (RELU) {
                v0 = fmaxf(v0, 0.f); v1 = fmaxf(v1, 0.f);
                v2 = fmaxf(v2, 0.f); v3 = fmaxf(v3, 0.f);
            }
            if (OUTF32) {
                float* C = (float*)Cout;
                *(float2*)(C + (size_t)row * ldc + col)       = make_float2(v0, v1);
                *(float2*)(C + (size_t)(row + 8) * ldc + col) = make_float2(v2, v3);
            } else {
                __half* C = (__half*)Cout;
                *(uint32_t*)(C + (size_t)row * ldc + col)       = packh2(v0, v1);
                *(uint32_t*)(C + (size_t)(row + 8) * ldc + col) = packh2(v2, v3);
            }
        }
    }
}

// ---------------------------------------------------------------------------
// Flash attention v2: 128-thread CTA, 4 warps, each warp owns 32 q-rows.
// K/V fragments loaded once per warp serve 2x16 q-rows -> half the LDS bytes.
// exp via ex2.approx.f16x2 (output doubles as packed P A-fragments).
// smem: Q 16KB + 2 stages x (K 8KB + V 8KB) = 48KB.
// ---------------------------------------------------------------------------
#define FL_SMEM (16384 + 2 * 16384)

__global__ __launch_bounds__(128, 2)
void flash_h(const __half* __restrict__ QH, const __half* __restrict__ KH,
             const __half* __restrict__ VH, __half* __restrict__ O)
{
    extern __shared__ char smc[];
    const uint32_t sb = smem_u32(smc);
    const int tid  = threadIdx.x;
    const int w    = tid >> 5;
    const int lane = tid & 31;
    const int qr   = lane >> 2;
    const int qc   = lane & 3;

    const int m0 = blockIdx.x * 128;
    const int bh = blockIdx.y;
    const size_t base = (size_t)(bh >> 3) * 2048 * 512 + (size_t)(bh & 7) * 64;

    // ---- Q tile: 128 rows x 64 halves (128B rows), swizzled ----
    {
        const __half* Qg = QH + base + (size_t)m0 * 512;
#pragma unroll
        for (int i = 0; i < 8; i++) {
            int u = tid + i * 128;
            int row = u >> 3, cu = u & 7;
            cp_async16(sb + sw128((uint32_t)(row << 7) + (uint32_t)(cu << 4)),
                       Qg + (size_t)row * 512 + cu * 8);
        }
        cp_commit();
    }
    auto load_kv = [&](int it, int s) {
        uint32_t kb = sb + 16384u + (uint32_t)s * 16384u;
        uint32_t vb = kb + 8192u;
        const __half* Kg = KH + base + (size_t)(it * 64) * 512;
        const __half* Vg = VH + base + (size_t)(it * 64) * 512;
#pragma unroll
        for (int i = 0; i < 4; i++) {
            int u = tid + i * 128;           // 0..511
            int row = u >> 3, cu = u & 7;
            uint32_t sw = sw128((uint32_t)(row << 7) + (uint32_t)(cu << 4));
            cp_async16(kb + sw, Kg + (size_t)row * 512 + cu * 8);
            cp_async16(vb + sw, Vg + (size_t)row * 512 + cu * 8);
        }
    };
    load_kv(0, 0);
    cp_commit();
    cp_wait<0>();
    __syncthreads();

    // ---- preload Q a-frags: warp w owns q-rows w*32..w*32+31 (2 m16 tiles) ----
    uint32_t aQ[2][4][4];
#pragma unroll
    for (int mt = 0; mt < 2; mt++)
#pragma unroll
        for (int j = 0; j < 4; j++) {
            int row = w * 32 + mt * 16 + (lane & 7) + ((lane >> 3) & 1) * 8;
            int unit = 2 * j + (lane >> 4);
            ldmx4(aQ[mt][j], sb + sw128((uint32_t)(row << 7) + (uint32_t)(unit << 4)));
        }

    const float c2 = 0.18033688011112042f;   // 0.125 * log2(e)
    float mst[2][2] = {{-1e30f, -1e30f}, {-1e30f, -1e30f}};
    float lst[2][2] = {{0.f, 0.f}, {0.f, 0.f}};
    float oacc[2][8][4];
#pragma unroll
    for (int mt = 0; mt < 2; mt++)
#pragma unroll
        for (int et = 0; et < 8; et++)
#pragma unroll
            for (int j = 0; j < 4; j++) oacc[mt][et][j] = 0.f;

    for (int it = 0; it < 32; ++it) {
        const int s = it & 1;
        if (it + 1 < 32) { load_kv(it + 1, s ^ 1); cp_commit(); cp_wait<1>(); }
        else             { cp_wait<0>(); }
        __syncthreads();

        uint32_t kb = sb + 16384u + (uint32_t)s * 16384u;
        uint32_t vb = kb + 8192u;

        // ---- S = Q @ K^T (raw, scale folded into exp) ----
        float s_[2][8][4];
#pragma unroll
        for (int mt = 0; mt < 2; mt++)
#pragma unroll
            for (int nt = 0; nt < 8; nt++)
#pragma unroll
                for (int j = 0; j < 4; j++) s_[mt][nt][j] = 0.f;
#pragma unroll
        for (int j = 0; j < 4; j++) {
            uint32_t bf[8][2];
#pragma unroll
            for (int p = 0; p < 4; p++) {
                uint32_t r[4];
                int row = p * 16 + (lane & 7) + ((lane >> 4) & 1) * 8;
                int unit = 2 * j + ((lane >> 3) & 1);
                ldmx4(r, kb + sw128((uint32_t)(row << 7) + (uint32_t)(unit << 4)));
                bf[2 * p][0] = r[0]; bf[2 * p][1] = r[1];
                bf[2 * p + 1][0] = r[2]; bf[2 * p + 1][1] = r[3];
            }
#pragma unroll
            for (int mt = 0; mt < 2; mt++)
#pragma unroll
                for (int nt = 0; nt < 8; nt++)
                    mma16(s_[mt][nt], aQ[mt][j], bf[nt]);
        }

        // ---- online softmax + f16x2 exp; pp = packed P A-frag halves ----
        uint32_t pp[2][8][2];
#pragma unroll
        for (int mt = 0; mt < 2; mt++) {
            float r0max = -1e30f, r1max = -1e30f;
#pragma unroll
            for (int nt = 0; nt < 8; nt++) {
                r0max = fmaxf(r0max, fmaxf(s_[mt][nt][0], s_[mt][nt][1]));
                r1max = fmaxf(r1max, fmaxf(s_[mt][nt][2], s_[mt][nt][3]));
            }
            r0max = fmaxf(r0max, __shfl_xor_sync(0xffffffffu, r0max, 1));
            r0max = fmaxf(r0max, __shfl_xor_sync(0xffffffffu, r0max, 2));
            r1max = fmaxf(r1max, __shfl_xor_sync(0xffffffffu, r1max, 1));
            r1max = fmaxf(r1max, __shfl_xor_sync(0xffffffffu, r1max, 2));

            float mn0 = fmaxf(mst[mt][0], r0max), mn1 = fmaxf(mst[mt][1], r1max);
            float al0 = exp2f((mst[mt][0] - mn0) * c2);
            float al1 = exp2f((mst[mt][1] - mn1) * c2);
            float mc0 = mn0 * c2, mc1 = mn1 * c2;
            float sum0 = 0.f, sum1 = 0.f;
#pragma unroll
            for (int nt = 0; nt < 8; nt++) {
                uint32_t e0 = h2exp2(packh2(fmaf(s_[mt][nt][0], c2, -mc0),
                                            fmaf(s_[mt][nt][1], c2, -mc0)));
                uint32_t e1 = h2exp2(packh2(fmaf(s_[mt][nt][2], c2, -mc1),
                                            fmaf(s_[mt][nt][3], c2, -mc1)));
                pp[mt][nt][0] = e0;
                pp[mt][nt][1] = e1;
                float2 f0 = h2tof2(e0); sum0 += f0.x + f0.y;
                float2 f1 = h2tof2(e1); sum1 += f1.x + f1.y;
            }
            sum0 += __shfl_xor_sync(0xffffffffu, sum0, 1);
            sum0 += __shfl_xor_sync(0xffffffffu, sum0, 2);
            sum1 += __shfl_xor_sync(0xffffffffu, sum1, 1);
            sum1 += __shfl_xor_sync(0xffffffffu, sum1, 2);

            lst[mt][0] = lst[mt][0] * al0 + sum0;  mst[mt][0] = mn0;
            lst[mt][1] = lst[mt][1] * al1 + sum1;  mst[mt][1] = mn1;
#pragma unroll
            for (int et = 0; et < 8; et++) {
                oacc[mt][et][0] *= al0; oacc[mt][et][1] *= al0;
                oacc[mt][et][2] *= al1; oacc[mt][et][3] *= al1;
            }
        }

        // ---- O += P @ V (V frags shared across mt) ----
#pragma unroll
        for (int j2 = 0; j2 < 4; j2++) {
            uint32_t pa[2][4];
#pragma unroll
            for (int mt = 0; mt < 2; mt++) {
                pa[mt][0] = pp[mt][2 * j2][0];
                pa[mt][1] = pp[mt][2 * j2][1];
                pa[mt][2] = pp[mt][2 * j2 + 1][0];
                pa[mt][3] = pp[mt][2 * j2 + 1][1];
            }
#pragma unroll
            for (int p = 0; p < 4; p++) {
                uint32_t r[4];
                int row = j2 * 16 + (lane & 7) + ((lane >> 3) & 1) * 8;  // key rows
                int unit = p * 2 + (lane >> 4);                           // e-units
                ldmx4t(r, vb + sw128((uint32_t)(row << 7) + (uint32_t)(unit << 4)));
                uint32_t bf0[2] = { r[0], r[1] };
                uint32_t bf1[2] = { r[2], r[3] };
#pragma unroll
                for (int mt = 0; mt < 2; mt++) {
                    mma16(oacc[mt][2 * p],     pa[mt], bf0);
                    mma16(oacc[mt][2 * p + 1], pa[mt], bf1);
                }
            }
        }
        __syncthreads();
    }

    __half* Og = O + base + (size_t)m0 * 512;
#pragma unroll
    for (int mt = 0; mt < 2; mt++) {
        const float i0 = 1.f / lst[mt][0];
        const float i1 = 1.f / lst[mt][1];
        int r0 = w * 32 + mt * 16 + qr;
#pragma unroll
        for (int et = 0; et < 8; et++) {
            int c = et * 8 + qc * 2;
            *(uint32_t*)(Og + (size_t)r0 * 512 + c)       = packh2(oacc[mt][et][0] * i0, oacc[mt][et][1] * i0);
            *(uint32_t*)(Og + (size_t)(r0 + 8) * 512 + c) = packh2(oacc[mt][et][2] * i1, oacc[mt][et][3] * i1);
        }
    }
}

// ---------------------------------------------------------------------------
// Launch
// ---------------------------------------------------------------------------
extern "C" void kernel_launch(void* const* d_in, const int* in_sizes, int n_in,
                              void* d_out, int out_size)
{
    const float* x1 = (const float*)d_in[0];
    const float* x2 = (const float*)d_in[1];
    const float* r  = (const float*)d_in[2];
    const float* W1 = (const float*)d_in[3];
    const float* b1 = (const float*)d_in[4];
    const float* W2 = (const float*)d_in[5];
    const float* b2 = (const float*)d_in[6];
    const float* Wq = (const float*)d_in[7];
    const float* Wk = (const float*)d_in[8];
    const float* Wv = (const float*)d_in[9];
    const float* Wo = (const float*)d_in[10];
    float* out = (float*)d_out;

    __half *H1, *H2, *Km, *Qm, *QH, *KH, *VH, *Ob;
    __half *x1h, *x2h, *rh, *W1t, *W2t, *Wqh, *Wkh, *Wvh, *Wot;
    cudaGetSymbolAddress((void**)&H1,  g_H1);
    cudaGetSymbolAddress((void**)&H2,  g_H2);
    cudaGetSymbolAddress((void**)&Km,  g_Km);
    cudaGetSymbolAddress((void**)&Qm,  g_Qm);
    cudaGetSymbolAddress((void**)&QH,  g_QH);
    cudaGetSymbolAddress((void**)&KH,  g_KH);
    cudaGetSymbolAddress((void**)&VH,  g_VH);
    cudaGetSymbolAddress((void**)&Ob,  g_O);
    cudaGetSymbolAddress((void**)&x1h, g_x1h);
    cudaGetSymbolAddress((void**)&x2h, g_x2h);
    cudaGetSymbolAddress((void**)&rh,  g_rh);
    cudaGetSymbolAddress((void**)&W1t, g_W1t);
    cudaGetSymbolAddress((void**)&W2t, g_W2t);
    cudaGetSymbolAddress((void**)&Wqh, g_Wqh);
    cudaGetSymbolAddress((void**)&Wkh, g_Wkh);
    cudaGetSymbolAddress((void**)&Wvh, g_Wvh);
    cudaGetSymbolAddress((void**)&Wot, g_Wot);

    cudaFuncSetAttribute(flash_h, cudaFuncAttributeMaxDynamicSharedMemorySize, FL_SMEM);
    cudaFuncSetAttribute((const void*)gemm_hb<true,  true,  false>, cudaFuncAttributeMaxDynamicSharedMemorySize, GEMM_SMEM);
    cudaFuncSetAttribute((const void*)gemm_hb<false, true,  false>, cudaFuncAttributeMaxDynamicSharedMemorySize, GEMM_SMEM);
    cudaFuncSetAttribute((const void*)gemm_hb<false, false, false>, cudaFuncAttributeMaxDynamicSharedMemorySize, GEMM_SMEM);
    cudaFuncSetAttribute((const void*)gemm_hb<false, false, true >, cudaFuncAttributeMaxDynamicSharedMemorySize, GEMM_SMEM);

    // --- pre-pass (2 launches) ---
    prep_inputs<<<dim3(1024, 1, 3), 256>>>((const float4*)x1, (const float4*)x2, (const float4*)r,
                                           (uint4*)x1h, (uint4*)x2h, (uint4*)rh);
    prep_weights<<<dim3(128, 1, 6), 256>>>(W1, W2, Wq, Wk, Wv, Wo,
                                           W1t, W2t, Wqh, Wkh, Wvh, Wot);

    // --- MLP layer 1 (x1, x2 batched) ---
    gemm_hb<true, true, false><<<dim3(4, 128, 2), 256, GEMM_SMEM>>>(
        x1h, x2h, x1h, W1t, W1t, W1t, b1, H1, H2, H1, 128, 512);
    // --- MLP layer 2 ---
    gemm_hb<false, true, false><<<dim3(4, 128, 2), 256, GEMM_SMEM>>>(
        H1, H2, H1, W2t, W2t, W2t, b2, Km, Qm, Km, 512, 512);
    // --- Q/K/V projections (batched) ---
    gemm_hb<false, false, false><<<dim3(4, 128, 3), 256, GEMM_SMEM>>>(
        Qm, Km, rh, Wqh, Wkh, Wvh, nullptr, QH, KH, VH, 512, 512);
    // --- attention ---
    flash_h<<<dim3(16, 64), 128, FL_SMEM>>>(QH, KH, VH, Ob);
    // --- output projection (f32 out) ---
    gemm_hb<false, false, true><<<dim3(4, 128, 1), 256, GEMM_SMEM>>>(
        Ob, Ob, Ob, Wot, Wot, Wot, nullptr, out, out, out, 512, 512);
}